// round 15
// baseline (speedup 1.0000x reference)
#include <cuda_runtime.h>
#include <cuda_fp16.h>
#include <cstdint>

// Problem constants (fixed shapes per reference setup_inputs)
#define BQ   2048      // queries
#define NK   100000    // capacity
#define DIM  128       // key size
#define TOPK 50
#define DELTA 1e-3f

#define NKP   100096                 // NK padded to multiple of 128 (782*128)
#define NBLK  (NKP / 64)             // 1564 64-key blocks
#define MARG  2.5f                   // screening margin (~5.8 sigma of int8 quant err)
#define CAP   4096
#define QS    20.0f                  // int8 quant scale (clip +-6.35)
#define INV2  (2.0f / (QS * QS))     // 0.005

// ---------------- scratch (static device globals; no runtime allocation) ----
__device__ __half   g_sh[(size_t)BQ * NKP];      // fp16 approx scores, 410 MB
__device__ int8_t   g_Qi[(size_t)BQ * DIM];
__device__ int8_t   g_Ki[(size_t)NKP * DIM];
__device__ float    g_bmin[(size_t)BQ * NBLK];   // per-(q, 64-block) min of stored fp16
__device__ float    g_keynorm[NK];
__device__ float    g_qnorm[BQ];
__device__ int      g_topk[BQ * TOPK];

static __device__ __forceinline__ float finf() { return __int_as_float(0x7f800000); }

static __device__ __forceinline__ uint32_t smem_u32(const void* p) {
    uint32_t a;
    asm("{ .reg .u64 t; cvta.to.shared.u64 t, %1; cvt.u32.u64 %0, t; }" : "=r"(a) : "l"(p));
    return a;
}

// ---------------- K0: row squared norms, XLA row-reduce replica (FROZEN) ----
__global__ void norms_kernel(const float* __restrict__ src, int rows, int which) {
    int warp = (blockIdx.x * blockDim.x + threadIdx.x) >> 5;
    int lane = threadIdx.x & 31;
    if (warp >= rows) return;
    const float* r = src + (size_t)warp * DIM;
    float acc = 0.f;
#pragma unroll
    for (int pass = 0; pass < 2; pass++) {
        int base = pass * 64 + 2 * lane;
        float v0 = r[base];
        float v1 = r[base + 1];
        acc = __fadd_rn(acc, __fmul_rn(v0, v0));
        acc = __fadd_rn(acc, __fmul_rn(v1, v1));
    }
#pragma unroll
    for (int s = 16; s; s >>= 1)
        acc = __fadd_rn(acc, __shfl_xor_sync(0xffffffffu, acc, s));
    if (lane == 0) {
        if (which == 0) g_keynorm[warp] = acc;
        else            g_qnorm[warp]   = acc;
    }
}

// ---------------- K0b: fp32 -> int8 quantize (zero-pad beyond n_src) --------
__global__ void cvt_s8(const float* __restrict__ src, int8_t* __restrict__ dst,
                       int n_src, int n_dst) {
    int i4 = (blockIdx.x * blockDim.x + threadIdx.x) * 4;
    if (i4 >= n_dst) return;
    float4 v = make_float4(0.f, 0.f, 0.f, 0.f);
    if (i4 + 3 < n_src) v = *(const float4*)(src + i4);
    else {
        if (i4 + 0 < n_src) v.x = src[i4 + 0];
        if (i4 + 1 < n_src) v.y = src[i4 + 1];
        if (i4 + 2 < n_src) v.z = src[i4 + 2];
        if (i4 + 3 < n_src) v.w = src[i4 + 3];
    }
    int b0 = __float2int_rn(fminf(fmaxf(v.x * QS, -127.f), 127.f));
    int b1 = __float2int_rn(fminf(fmaxf(v.y * QS, -127.f), 127.f));
    int b2 = __float2int_rn(fminf(fmaxf(v.z * QS, -127.f), 127.f));
    int b3 = __float2int_rn(fminf(fmaxf(v.w * QS, -127.f), 127.f));
    uint32_t p = (uint32_t)(b0 & 0xff) | ((uint32_t)(b1 & 0xff) << 8)
               | ((uint32_t)(b2 & 0xff) << 16) | ((uint32_t)(b3 & 0xff) << 24);
    *(uint32_t*)(dst + i4) = p;
}

// ---------------- K1: int8 IMMA screening GEMM ------------------------------
// CTA: 128 q x 128 k, 8 warps. Warp tile: 32m x 64n. K=128 int8, 4 k32 steps.
// s~ = qn - INV2*idot + kn (exact fp32 norms + exact s32 dot of quantized),
// fp16 store + 64-block mins.
#define SAS 144   // smem row stride BYTES (128 data + 16 pad; ldmatrix conflict-free)

static __device__ __forceinline__ void imma16832(int acc[4],
                                                 uint32_t a0, uint32_t a1, uint32_t a2, uint32_t a3,
                                                 uint32_t b0, uint32_t b1) {
    asm volatile(
        "mma.sync.aligned.m16n8k32.row.col.s32.s8.s8.s32 "
        "{%0,%1,%2,%3}, {%4,%5,%6,%7}, {%8,%9}, {%0,%1,%2,%3};\n"
        : "+r"(acc[0]), "+r"(acc[1]), "+r"(acc[2]), "+r"(acc[3])
        : "r"(a0), "r"(a1), "r"(a2), "r"(a3), "r"(b0), "r"(b1));
}
static __device__ __forceinline__ void ldsm_x4(uint32_t& r0, uint32_t& r1,
                                               uint32_t& r2, uint32_t& r3, uint32_t addr) {
    asm volatile("ldmatrix.sync.aligned.m8n8.x4.shared.b16 {%0,%1,%2,%3}, [%4];"
                 : "=r"(r0), "=r"(r1), "=r"(r2), "=r"(r3) : "r"(addr));
}

__global__ __launch_bounds__(256) void screen_gemm() {
    __shared__ __align__(16) int8_t smA[128 * SAS];
    __shared__ __align__(16) int8_t smB[128 * SAS];
    uint32_t smbA = smem_u32(smA);
    uint32_t smbB = smem_u32(smB);

    int tid  = threadIdx.x;
    int wid  = tid >> 5;
    int lane = tid & 31;
    int warpM = wid & 3;   // 32 q rows each
    int warpN = wid >> 2;  // 64 k cols each
    int n0   = blockIdx.x * 128;
    int b0q  = blockIdx.y * 128;

    // stage A (128 q rows) and B (128 key rows): 128 B data per row, 16B chunks
    for (int i = tid; i < 128 * 8; i += 256) {
        int row = i >> 3, ch = i & 7;
        uint4 va = *(const uint4*)(g_Qi + (size_t)(b0q + row) * DIM + ch * 16);
        *(uint4*)(smA + row * SAS + ch * 16) = va;
        uint4 vb = *(const uint4*)(g_Ki + (size_t)(n0 + row) * DIM + ch * 16);
        *(uint4*)(smB + row * SAS + ch * 16) = vb;
    }
    __syncthreads();

    int acc[2][8][4];
#pragma unroll
    for (int mi = 0; mi < 2; mi++)
#pragma unroll
        for (int ni = 0; ni < 8; ni++)
#pragma unroll
            for (int j = 0; j < 4; j++) acc[mi][ni][j] = 0;

    int lg = lane >> 3;   // ldmatrix submatrix group 0..3
    int lr = lane & 7;    // row within group

#pragma unroll
    for (int ks = 0; ks < 4; ks++) {
        int k0 = ks * 32;
        // A fragments: per mi, rows warpM*32+mi*16 .. +15, 32 bytes of k
        // groups: g0 rows0-7@k0, g1 rows8-15@k0, g2 rows0-7@k0+16, g3 rows8-15@k0+16
        uint32_t a[2][4];
#pragma unroll
        for (int mi = 0; mi < 2; mi++) {
            int arow = warpM * 32 + mi * 16 + (lg & 1) * 8 + lr;
            uint32_t ad = smbA + (uint32_t)(arow * SAS + k0 + (lg >> 1) * 16);
            ldsm_x4(a[mi][0], a[mi][1], a[mi][2], a[mi][3], ad);
        }
        // B fragments: per j, 16 keys (2 n8 blocks)
        // groups: g0 rows0-7@k0 (b0 blk0), g1 rows0-7@k0+16 (b1 blk0),
        //         g2 rows8-15@k0 (b0 blk1), g3 rows8-15@k0+16 (b1 blk1)
#pragma unroll
        for (int j = 0; j < 4; j++) {
            int brow = warpN * 64 + j * 16 + (lg >> 1) * 8 + lr;
            uint32_t bd = smbB + (uint32_t)(brow * SAS + k0 + (lg & 1) * 16);
            uint32_t b0, b1, b2, b3;
            ldsm_x4(b0, b1, b2, b3, bd);
#pragma unroll
            for (int mi = 0; mi < 2; mi++) {
                imma16832(acc[mi][2 * j + 0], a[mi][0], a[mi][1], a[mi][2], a[mi][3], b0, b1);
                imma16832(acc[mi][2 * j + 1], a[mi][0], a[mi][1], a[mi][2], a[mi][3], b2, b3);
            }
        }
    }

    // epilogue: s~ = qn - INV2*idot + kn ; fp16 store + 64-block min
    int colbase = n0 + warpN * 64;
#pragma unroll
    for (int mi = 0; mi < 2; mi++) {
#pragma unroll
        for (int rr = 0; rr < 2; rr++) {
            int q  = b0q + warpM * 32 + mi * 16 + rr * 8 + (lane >> 2);
            float qn = g_qnorm[q];
            float mn = finf();
            __half* dst = g_sh + (size_t)q * NKP;
#pragma unroll
            for (int ni = 0; ni < 8; ni++) {
                int gn = colbase + ni * 8 + 2 * (lane & 3);
                float d0 = (float)acc[mi][ni][2 * rr + 0];
                float d1 = (float)acc[mi][ni][2 * rr + 1];
                float s0 = (gn     < NK) ? (qn - INV2 * d0 + g_keynorm[gn])     : finf();
                float s1 = (gn + 1 < NK) ? (qn - INV2 * d1 + g_keynorm[gn + 1]) : finf();
                __half h0 = __float2half(s0), h1 = __float2half(s1);
                __half2 p; p.x = h0; p.y = h1;
                *(__half2*)(dst + gn) = p;
                mn = fminf(mn, fminf(__half2float(h0), __half2float(h1)));
            }
#pragma unroll
            for (int s = 1; s < 4; s <<= 1)
                mn = fminf(mn, __shfl_xor_sync(0xffffffffu, mn, s));
            if ((lane & 3) == 0)
                g_bmin[(size_t)q * NBLK + blockIdx.x * 2 + warpN] = mn;
        }
    }
}

// ---------------- K2: select via screen + EXACT frozen-chain rescore --------
__global__ __launch_bounds__(256) void topk_sel(const float* __restrict__ Q,
                                                const float* __restrict__ Kd) {
    int b    = blockIdx.x;
    int tid  = threadIdx.x;
    int w    = tid >> 5;
    int lane = tid & 31;

    __shared__ float smin[256];
    __shared__ float sv[CAP];
    __shared__ int   si[CAP];
    __shared__ float qrow[DIM];
    __shared__ float kbuf[8][DIM];
    __shared__ int   s_cnt;

    const float* bm = g_bmin + (size_t)b * NBLK;

    // ---- pass 1: tau from block minima ----
    float m = finf();
    for (int p = tid; p < NBLK; p += 256) m = fminf(m, bm[p]);
    smin[tid] = m;
    if (tid == 0) s_cnt = 0;
    for (int k = tid; k < DIM; k += 256) qrow[k] = Q[(size_t)b * DIM + k];
    __syncthreads();

    for (int k = 2; k <= 256; k <<= 1) {
        for (int j = k >> 1; j; j >>= 1) {
            int ixj = tid ^ j;
            if (ixj > tid) {
                float v1 = smin[tid], v2 = smin[ixj];
                bool up = ((tid & k) == 0);
                if ((v1 < v2) != up) { smin[tid] = v2; smin[ixj] = v1; }
            }
            __syncthreads();
        }
    }
    float T2 = smin[TOPK - 1] + 2.f * MARG;   // superset threshold
    __syncthreads();

    // ---- pass 2: candidates from fp16 screen matrix (warp per block) ----
    const __half* srow = g_sh + (size_t)b * NKP;
    for (int p = w; p < NBLK; p += 8) {
        if (bm[p] <= T2) {
            int nb = p * 64 + lane * 2;
            __half2 h2 = *(const __half2*)(srow + nb);
            float f0 = __half2float(h2.x);
            float f1 = __half2float(h2.y);
            if (nb < NK && f0 <= T2) {
                int q = atomicAdd(&s_cnt, 1);
                if (q < CAP) si[q] = nb;
            }
            if (nb + 1 < NK && f1 <= T2) {
                int q = atomicAdd(&s_cnt, 1);
                if (q < CAP) si[q] = nb + 1;
            }
        }
    }
    __syncthreads();
    int cnt = s_cnt; if (cnt > CAP) cnt = CAP;

    // ---- exact rescore with the FROZEN chain (warp per candidate) ----
    float qn = g_qnorm[b];
    for (int c = w; c < cnt; c += 8) {
        int n = si[c];
        float4 kv = *(const float4*)(Kd + (size_t)n * DIM + lane * 4);
        *(float4*)&kbuf[w][lane * 4] = kv;
        __syncwarp();
        if (lane == 0) {
            float acc = 0.f;
#pragma unroll
            for (int k = 0; k < DIM; k++)
                acc = fmaf(qrow[k], kbuf[w][k], acc);   // ascending k, FMA — frozen
            sv[c] = __fadd_rn(__fsub_rn(qn, 2.f * acc), g_keynorm[n]);
        }
        __syncwarp();
    }
    __syncthreads();

    int P = 64; while (P < cnt) P <<= 1;
    for (int i = tid; i < P; i += 256)
        if (i >= cnt) { sv[i] = finf(); si[i] = 0x7fffffff; }
    __syncthreads();

    // bitonic sort by (value, index) ascending — canonical, deterministic
    for (int k = 2; k <= P; k <<= 1) {
        for (int j = k >> 1; j; j >>= 1) {
            for (int i = tid; i < P; i += 256) {
                int ixj = i ^ j;
                if (ixj > i) {
                    float v1 = sv[i], v2 = sv[ixj];
                    int  i1 = si[i],  i2 = si[ixj];
                    bool up   = ((i & k) == 0);
                    bool less = (v1 < v2) || (v1 == v2 && i1 < i2);
                    if (less != up) {
                        sv[i] = v2; sv[ixj] = v1;
                        si[i] = i2; si[ixj] = i1;
                    }
                }
            }
            __syncthreads();
        }
    }

    if (tid < TOPK) {
        int ki = si[tid];
        if (ki < 0) ki = 0;
        if (ki >= NK) ki = NK - 1;   // fail-soft: never emit OOB index
        g_topk[b * TOPK + tid] = ki;
    }
}

// ---------------- K3: fp32 recompute (as reference) + weighting (FROZEN) ----
__global__ __launch_bounds__(128) void out_kernel(const float* __restrict__ Q,
                                                  const float* __restrict__ Kd,
                                                  const float* __restrict__ V,
                                                  float* __restrict__ out) {
    int b    = blockIdx.x;
    int lane = threadIdx.x & 31;
    int warp = threadIdx.x >> 5;
    __shared__ float sqd[TOPK];

    const float* qr = Q + (size_t)b * DIM;
    for (int j = warp; j < TOPK; j += 4) {
        int ki = g_topk[b * TOPK + j];
        const float* kr = Kd + (size_t)ki * DIM;
        float acc = 0.f;
#pragma unroll
        for (int m = 0; m < 4; m++) {
            float d = qr[lane + 32 * m] - kr[lane + 32 * m];
            float p = __fmul_rn(d, d);
            acc = __fadd_rn(acc, p);
        }
#pragma unroll
        for (int s = 16; s; s >>= 1) acc += __shfl_xor_sync(0xffffffffu, acc, s);
        if (lane == 0) sqd[j] = acc;
    }
    __syncthreads();

    if (threadIdx.x == 0) {
        float s1 = 0.f, s2 = 0.f;
        for (int j = 0; j < TOPK; j++) {
            float w = 1.f / (sqd[j] + DELTA);
            s1 += w;
            s2 += w * V[g_topk[b * TOPK + j]];
        }
        out[b] = s2 / s1;
    }
}

// ---------------- launch ----------------------------------------------------
extern "C" void kernel_launch(void* const* d_in, const int* in_sizes, int n_in,
                              void* d_out, int out_size) {
    const float* Q  = nullptr;   // 262144 elems
    const float* Kd = nullptr;   // 12800000 elems
    const float* V  = nullptr;   // 100000 elems
    for (int i = 0; i < n_in; i++) {
        if      (in_sizes[i] == BQ * DIM) Q  = (const float*)d_in[i];
        else if (in_sizes[i] == NK * DIM) Kd = (const float*)d_in[i];
        else if (in_sizes[i] == NK)       V  = (const float*)d_in[i];
    }
    float* out = (float*)d_out;
    if (!Q || !Kd || !V) return;

    norms_kernel<<<(NK + 7) / 8, 256>>>(Kd, NK, 0);
    norms_kernel<<<(BQ + 7) / 8, 256>>>(Q,  BQ, 1);

    // int8 quantized copies (zero-padded keys)
    {
        int8_t* qi = nullptr; cudaGetSymbolAddress((void**)&qi, g_Qi);
        int8_t* ki = nullptr; cudaGetSymbolAddress((void**)&ki, g_Ki);
        int nq = BQ * DIM;
        int nk = NKP * DIM;
        cvt_s8<<<(nq / 4 + 255) / 256, 256>>>(Q,  qi, nq,       nq);
        cvt_s8<<<(nk / 4 + 255) / 256, 256>>>(Kd, ki, NK * DIM, nk);
    }

    dim3 sgrid(NKP / 128, BQ / 128);   // 782 x 16
    screen_gemm<<<sgrid, 256>>>();

    topk_sel<<<BQ, 256>>>(Q, Kd);

    out_kernel<<<BQ, 128>>>(Q, Kd, V, out);
}

// round 16
// speedup vs baseline: 1.0041x; 1.0041x over previous
#include <cuda_runtime.h>
#include <cuda_fp16.h>
#include <cstdint>

// Problem constants (fixed shapes per reference setup_inputs)
#define BQ   2048      // queries
#define NK   100000    // capacity
#define DIM  128       // key size
#define TOPK 50
#define DELTA 1e-3f

#define NKP   100096                 // NK padded to multiple of 128 (782*128)
#define NBLK  (NKP / 64)             // 1564 64-key blocks
#define MARG  2.5f                   // screening margin (~5.8 sigma of int8 quant err)
#define CAP   4096
#define QS    20.0f                  // int8 quant scale (clip +-6.35)
#define INV2  (2.0f / (QS * QS))     // 0.005

// ---------------- scratch (static device globals; no runtime allocation) ----
__device__ __half   g_sh[(size_t)BQ * NKP];      // fp16 approx scores, 410 MB
__device__ int8_t   g_Qi[(size_t)BQ * DIM];
__device__ int8_t   g_Ki[(size_t)NKP * DIM];
__device__ float    g_bmin[(size_t)BQ * NBLK];   // per-(q, 64-block) min of stored fp16
__device__ float    g_keynorm[NK];
__device__ float    g_qnorm[BQ];
__device__ int      g_topk[BQ * TOPK];

static __device__ __forceinline__ float finf() { return __int_as_float(0x7f800000); }

static __device__ __forceinline__ uint32_t smem_u32(const void* p) {
    uint32_t a;
    asm("{ .reg .u64 t; cvta.to.shared.u64 t, %1; cvt.u32.u64 %0, t; }" : "=r"(a) : "l"(p));
    return a;
}

// ---------------- K0: row squared norms, XLA row-reduce replica (FROZEN) ----
__global__ void norms_kernel(const float* __restrict__ src, int rows, int which) {
    int warp = (blockIdx.x * blockDim.x + threadIdx.x) >> 5;
    int lane = threadIdx.x & 31;
    if (warp >= rows) return;
    const float* r = src + (size_t)warp * DIM;
    float acc = 0.f;
#pragma unroll
    for (int pass = 0; pass < 2; pass++) {
        int base = pass * 64 + 2 * lane;
        float v0 = r[base];
        float v1 = r[base + 1];
        acc = __fadd_rn(acc, __fmul_rn(v0, v0));
        acc = __fadd_rn(acc, __fmul_rn(v1, v1));
    }
#pragma unroll
    for (int s = 16; s; s >>= 1)
        acc = __fadd_rn(acc, __shfl_xor_sync(0xffffffffu, acc, s));
    if (lane == 0) {
        if (which == 0) g_keynorm[warp] = acc;
        else            g_qnorm[warp]   = acc;
    }
}

// ---------------- K0b: fp32 -> int8 quantize (zero-pad beyond n_src) --------
__global__ void cvt_s8(const float* __restrict__ src, int8_t* __restrict__ dst,
                       int n_src, int n_dst) {
    int i4 = (blockIdx.x * blockDim.x + threadIdx.x) * 4;
    if (i4 >= n_dst) return;
    float4 v = make_float4(0.f, 0.f, 0.f, 0.f);
    if (i4 + 3 < n_src) v = *(const float4*)(src + i4);
    else {
        if (i4 + 0 < n_src) v.x = src[i4 + 0];
        if (i4 + 1 < n_src) v.y = src[i4 + 1];
        if (i4 + 2 < n_src) v.z = src[i4 + 2];
        if (i4 + 3 < n_src) v.w = src[i4 + 3];
    }
    int b0 = __float2int_rn(fminf(fmaxf(v.x * QS, -127.f), 127.f));
    int b1 = __float2int_rn(fminf(fmaxf(v.y * QS, -127.f), 127.f));
    int b2 = __float2int_rn(fminf(fmaxf(v.z * QS, -127.f), 127.f));
    int b3 = __float2int_rn(fminf(fmaxf(v.w * QS, -127.f), 127.f));
    uint32_t p = (uint32_t)(b0 & 0xff) | ((uint32_t)(b1 & 0xff) << 8)
               | ((uint32_t)(b2 & 0xff) << 16) | ((uint32_t)(b3 & 0xff) << 24);
    *(uint32_t*)(dst + i4) = p;
}

// ---------------- K1: int8 IMMA screening GEMM ------------------------------
// CTA: 128 q x 128 k, 8 warps. Warp tile: 32m x 64n. K=128 int8, 4 k32 steps.
// s~ = qn - INV2*idot + kn (exact fp32 norms + exact s32 dot of quantized),
// fp16 store + 64-block mins.
#define SAS 144   // smem row stride BYTES (128 data + 16 pad; ldmatrix conflict-free)

static __device__ __forceinline__ void imma16832(int acc[4],
                                                 uint32_t a0, uint32_t a1, uint32_t a2, uint32_t a3,
                                                 uint32_t b0, uint32_t b1) {
    asm volatile(
        "mma.sync.aligned.m16n8k32.row.col.s32.s8.s8.s32 "
        "{%0,%1,%2,%3}, {%4,%5,%6,%7}, {%8,%9}, {%0,%1,%2,%3};\n"
        : "+r"(acc[0]), "+r"(acc[1]), "+r"(acc[2]), "+r"(acc[3])
        : "r"(a0), "r"(a1), "r"(a2), "r"(a3), "r"(b0), "r"(b1));
}
static __device__ __forceinline__ void ldsm_x4(uint32_t& r0, uint32_t& r1,
                                               uint32_t& r2, uint32_t& r3, uint32_t addr) {
    asm volatile("ldmatrix.sync.aligned.m8n8.x4.shared.b16 {%0,%1,%2,%3}, [%4];"
                 : "=r"(r0), "=r"(r1), "=r"(r2), "=r"(r3) : "r"(addr));
}

__global__ __launch_bounds__(256) void screen_gemm() {
    __shared__ __align__(16) int8_t smA[128 * SAS];
    __shared__ __align__(16) int8_t smB[128 * SAS];
    uint32_t smbA = smem_u32(smA);
    uint32_t smbB = smem_u32(smB);

    int tid  = threadIdx.x;
    int wid  = tid >> 5;
    int lane = tid & 31;
    int warpM = wid & 3;   // 32 q rows each
    int warpN = wid >> 2;  // 64 k cols each
    int n0   = blockIdx.x * 128;
    int b0q  = blockIdx.y * 128;

    // stage A (128 q rows) and B (128 key rows): 128 B data per row, 16B chunks
    for (int i = tid; i < 128 * 8; i += 256) {
        int row = i >> 3, ch = i & 7;
        uint4 va = *(const uint4*)(g_Qi + (size_t)(b0q + row) * DIM + ch * 16);
        *(uint4*)(smA + row * SAS + ch * 16) = va;
        uint4 vb = *(const uint4*)(g_Ki + (size_t)(n0 + row) * DIM + ch * 16);
        *(uint4*)(smB + row * SAS + ch * 16) = vb;
    }
    __syncthreads();

    int acc[2][8][4];
#pragma unroll
    for (int mi = 0; mi < 2; mi++)
#pragma unroll
        for (int ni = 0; ni < 8; ni++)
#pragma unroll
            for (int j = 0; j < 4; j++) acc[mi][ni][j] = 0;

    int lg = lane >> 3;   // ldmatrix submatrix group 0..3
    int lr = lane & 7;    // row within group

#pragma unroll
    for (int ks = 0; ks < 4; ks++) {
        int k0 = ks * 32;
        // A fragments: per mi, rows warpM*32+mi*16 .. +15, 32 bytes of k
        // groups: g0 rows0-7@k0, g1 rows8-15@k0, g2 rows0-7@k0+16, g3 rows8-15@k0+16
        uint32_t a[2][4];
#pragma unroll
        for (int mi = 0; mi < 2; mi++) {
            int arow = warpM * 32 + mi * 16 + (lg & 1) * 8 + lr;
            uint32_t ad = smbA + (uint32_t)(arow * SAS + k0 + (lg >> 1) * 16);
            ldsm_x4(a[mi][0], a[mi][1], a[mi][2], a[mi][3], ad);
        }
        // B fragments: per j, 16 keys (2 n8 blocks)
        // groups: g0 rows0-7@k0 (b0 blk0), g1 rows0-7@k0+16 (b1 blk0),
        //         g2 rows8-15@k0 (b0 blk1), g3 rows8-15@k0+16 (b1 blk1)
#pragma unroll
        for (int j = 0; j < 4; j++) {
            int brow = warpN * 64 + j * 16 + (lg >> 1) * 8 + lr;
            uint32_t bd = smbB + (uint32_t)(brow * SAS + k0 + (lg & 1) * 16);
            uint32_t b0, b1, b2, b3;
            ldsm_x4(b0, b1, b2, b3, bd);
#pragma unroll
            for (int mi = 0; mi < 2; mi++) {
                imma16832(acc[mi][2 * j + 0], a[mi][0], a[mi][1], a[mi][2], a[mi][3], b0, b1);
                imma16832(acc[mi][2 * j + 1], a[mi][0], a[mi][1], a[mi][2], a[mi][3], b2, b3);
            }
        }
    }

    // epilogue: s~ = qn - INV2*idot + kn ; fp16 store + 64-block min
    int colbase = n0 + warpN * 64;
#pragma unroll
    for (int mi = 0; mi < 2; mi++) {
#pragma unroll
        for (int rr = 0; rr < 2; rr++) {
            int q  = b0q + warpM * 32 + mi * 16 + rr * 8 + (lane >> 2);
            float qn = g_qnorm[q];
            float mn = finf();
            __half* dst = g_sh + (size_t)q * NKP;
#pragma unroll
            for (int ni = 0; ni < 8; ni++) {
                int gn = colbase + ni * 8 + 2 * (lane & 3);
                float d0 = (float)acc[mi][ni][2 * rr + 0];
                float d1 = (float)acc[mi][ni][2 * rr + 1];
                float s0 = (gn     < NK) ? (qn - INV2 * d0 + g_keynorm[gn])     : finf();
                float s1 = (gn + 1 < NK) ? (qn - INV2 * d1 + g_keynorm[gn + 1]) : finf();
                __half h0 = __float2half(s0), h1 = __float2half(s1);
                __half2 p; p.x = h0; p.y = h1;
                *(__half2*)(dst + gn) = p;
                mn = fminf(mn, fminf(__half2float(h0), __half2float(h1)));
            }
#pragma unroll
            for (int s = 1; s < 4; s <<= 1)
                mn = fminf(mn, __shfl_xor_sync(0xffffffffu, mn, s));
            if ((lane & 3) == 0)
                g_bmin[(size_t)q * NBLK + blockIdx.x * 2 + warpN] = mn;
        }
    }
}

// ---------------- K2: select via screen + EXACT frozen-chain rescore --------
__global__ __launch_bounds__(256) void topk_sel(const float* __restrict__ Q,
                                                const float* __restrict__ Kd) {
    int b    = blockIdx.x;
    int tid  = threadIdx.x;
    int w    = tid >> 5;
    int lane = tid & 31;

    __shared__ float smin[256];
    __shared__ float sv[CAP];
    __shared__ int   si[CAP];
    __shared__ float qrow[DIM];
    __shared__ float kbuf[8][DIM];
    __shared__ int   s_cnt;

    const float* bm = g_bmin + (size_t)b * NBLK;

    // ---- pass 1: tau from block minima ----
    float m = finf();
    for (int p = tid; p < NBLK; p += 256) m = fminf(m, bm[p]);
    smin[tid] = m;
    if (tid == 0) s_cnt = 0;
    for (int k = tid; k < DIM; k += 256) qrow[k] = Q[(size_t)b * DIM + k];
    __syncthreads();

    for (int k = 2; k <= 256; k <<= 1) {
        for (int j = k >> 1; j; j >>= 1) {
            int ixj = tid ^ j;
            if (ixj > tid) {
                float v1 = smin[tid], v2 = smin[ixj];
                bool up = ((tid & k) == 0);
                if ((v1 < v2) != up) { smin[tid] = v2; smin[ixj] = v1; }
            }
            __syncthreads();
        }
    }
    float T2 = smin[TOPK - 1] + 2.f * MARG;   // superset threshold
    __syncthreads();

    // ---- pass 2: candidates from fp16 screen matrix (warp per block) ----
    const __half* srow = g_sh + (size_t)b * NKP;
    for (int p = w; p < NBLK; p += 8) {
        if (bm[p] <= T2) {
            int nb = p * 64 + lane * 2;
            __half2 h2 = *(const __half2*)(srow + nb);
            float f0 = __half2float(h2.x);
            float f1 = __half2float(h2.y);
            if (nb < NK && f0 <= T2) {
                int q = atomicAdd(&s_cnt, 1);
                if (q < CAP) si[q] = nb;
            }
            if (nb + 1 < NK && f1 <= T2) {
                int q = atomicAdd(&s_cnt, 1);
                if (q < CAP) si[q] = nb + 1;
            }
        }
    }
    __syncthreads();
    int cnt = s_cnt; if (cnt > CAP) cnt = CAP;

    // ---- exact rescore with the FROZEN chain (warp per candidate) ----
    float qn = g_qnorm[b];
    for (int c = w; c < cnt; c += 8) {
        int n = si[c];
        float4 kv = *(const float4*)(Kd + (size_t)n * DIM + lane * 4);
        *(float4*)&kbuf[w][lane * 4] = kv;
        __syncwarp();
        if (lane == 0) {
            float acc = 0.f;
#pragma unroll
            for (int k = 0; k < DIM; k++)
                acc = fmaf(qrow[k], kbuf[w][k], acc);   // ascending k, FMA — frozen
            sv[c] = __fadd_rn(__fsub_rn(qn, 2.f * acc), g_keynorm[n]);
        }
        __syncwarp();
    }
    __syncthreads();

    int P = 64; while (P < cnt) P <<= 1;
    for (int i = tid; i < P; i += 256)
        if (i >= cnt) { sv[i] = finf(); si[i] = 0x7fffffff; }
    __syncthreads();

    // bitonic sort by (value, index) ascending — canonical, deterministic
    for (int k = 2; k <= P; k <<= 1) {
        for (int j = k >> 1; j; j >>= 1) {
            for (int i = tid; i < P; i += 256) {
                int ixj = i ^ j;
                if (ixj > i) {
                    float v1 = sv[i], v2 = sv[ixj];
                    int  i1 = si[i],  i2 = si[ixj];
                    bool up   = ((i & k) == 0);
                    bool less = (v1 < v2) || (v1 == v2 && i1 < i2);
                    if (less != up) {
                        sv[i] = v2; sv[ixj] = v1;
                        si[i] = i2; si[ixj] = i1;
                    }
                }
            }
            __syncthreads();
        }
    }

    if (tid < TOPK) {
        int ki = si[tid];
        if (ki < 0) ki = 0;
        if (ki >= NK) ki = NK - 1;   // fail-soft: never emit OOB index
        g_topk[b * TOPK + tid] = ki;
    }
}

// ---------------- K3: fp32 recompute (as reference) + weighting (FROZEN) ----
__global__ __launch_bounds__(128) void out_kernel(const float* __restrict__ Q,
                                                  const float* __restrict__ Kd,
                                                  const float* __restrict__ V,
                                                  float* __restrict__ out) {
    int b    = blockIdx.x;
    int lane = threadIdx.x & 31;
    int warp = threadIdx.x >> 5;
    __shared__ float sqd[TOPK];

    const float* qr = Q + (size_t)b * DIM;
    for (int j = warp; j < TOPK; j += 4) {
        int ki = g_topk[b * TOPK + j];
        const float* kr = Kd + (size_t)ki * DIM;
        float acc = 0.f;
#pragma unroll
        for (int m = 0; m < 4; m++) {
            float d = qr[lane + 32 * m] - kr[lane + 32 * m];
            float p = __fmul_rn(d, d);
            acc = __fadd_rn(acc, p);
        }
#pragma unroll
        for (int s = 16; s; s >>= 1) acc += __shfl_xor_sync(0xffffffffu, acc, s);
        if (lane == 0) sqd[j] = acc;
    }
    __syncthreads();

    if (threadIdx.x == 0) {
        float s1 = 0.f, s2 = 0.f;
        for (int j = 0; j < TOPK; j++) {
            float w = 1.f / (sqd[j] + DELTA);
            s1 += w;
            s2 += w * V[g_topk[b * TOPK + j]];
        }
        out[b] = s2 / s1;
    }
}

// ---------------- launch ----------------------------------------------------
extern "C" void kernel_launch(void* const* d_in, const int* in_sizes, int n_in,
                              void* d_out, int out_size) {
    const float* Q  = nullptr;   // 262144 elems
    const float* Kd = nullptr;   // 12800000 elems
    const float* V  = nullptr;   // 100000 elems
    for (int i = 0; i < n_in; i++) {
        if      (in_sizes[i] == BQ * DIM) Q  = (const float*)d_in[i];
        else if (in_sizes[i] == NK * DIM) Kd = (const float*)d_in[i];
        else if (in_sizes[i] == NK)       V  = (const float*)d_in[i];
    }
    float* out = (float*)d_out;
    if (!Q || !Kd || !V) return;

    norms_kernel<<<(NK + 7) / 8, 256>>>(Kd, NK, 0);
    norms_kernel<<<(BQ + 7) / 8, 256>>>(Q,  BQ, 1);

    // int8 quantized copies (zero-padded keys)
    {
        int8_t* qi = nullptr; cudaGetSymbolAddress((void**)&qi, g_Qi);
        int8_t* ki = nullptr; cudaGetSymbolAddress((void**)&ki, g_Ki);
        int nq = BQ * DIM;
        int nk = NKP * DIM;
        cvt_s8<<<(nq / 4 + 255) / 256, 256>>>(Q,  qi, nq,       nq);
        cvt_s8<<<(nk / 4 + 255) / 256, 256>>>(Kd, ki, NK * DIM, nk);
    }

    dim3 sgrid(NKP / 128, BQ / 128);   // 782 x 16
    screen_gemm<<<sgrid, 256>>>();

    topk_sel<<<BQ, 256>>>(Q, Kd);

    out_kernel<<<BQ, 128>>>(Q, Kd, V, out);
}

// round 17
// speedup vs baseline: 1.2651x; 1.2600x over previous
#include <cuda_runtime.h>
#include <cuda_fp16.h>
#include <cuda_bf16.h>
#include <cstdint>

// Problem constants (fixed shapes per reference setup_inputs)
#define BQ   2048      // queries
#define NK   100000    // capacity
#define DIM  128       // key size
#define TOPK 50
#define DELTA 1e-3f

#define NKP   100096                 // NK padded to multiple of 128 (782*128)
#define NBLK  (NKP / 64)             // 1564 64-key blocks
#define MARG  0.75f                  // screening error margin (>= bf16+fp16 err)
#define CAP   4096

// ---------------- scratch (static device globals; no runtime allocation) ----
__device__ __half         g_sh[(size_t)BQ * NKP];      // fp16 approx scores, 410 MB
__device__ __nv_bfloat16  g_Qb[(size_t)BQ * DIM];
__device__ __nv_bfloat16  g_Kb[(size_t)NKP * DIM];
__device__ float          g_bmin[(size_t)BQ * NBLK];   // per-(q, 64-block) min of stored fp16
__device__ float          g_keynorm[NK];
__device__ float          g_qnorm[BQ];
__device__ int            g_topk[BQ * TOPK];

static __device__ __forceinline__ float finf() { return __int_as_float(0x7f800000); }

static __device__ __forceinline__ uint32_t smem_u32(const void* p) {
    uint32_t a;
    asm("{ .reg .u64 t; cvta.to.shared.u64 t, %1; cvt.u32.u64 %0, t; }" : "=r"(a) : "l"(p));
    return a;
}
static __device__ __forceinline__ void stg_cs_v4(void* gptr, uint4 v) {
    asm volatile("st.global.cs.v4.u32 [%0], {%1,%2,%3,%4};"
                 :: "l"(gptr), "r"(v.x), "r"(v.y), "r"(v.z), "r"(v.w) : "memory");
}

// ---------------- K0: row squared norms, XLA row-reduce replica (FROZEN) ----
__global__ void norms_kernel(const float* __restrict__ src, int rows, int which) {
    int warp = (blockIdx.x * blockDim.x + threadIdx.x) >> 5;
    int lane = threadIdx.x & 31;
    if (warp >= rows) return;
    const float* r = src + (size_t)warp * DIM;
    float acc = 0.f;
#pragma unroll
    for (int pass = 0; pass < 2; pass++) {
        int base = pass * 64 + 2 * lane;
        float v0 = r[base];
        float v1 = r[base + 1];
        acc = __fadd_rn(acc, __fmul_rn(v0, v0));
        acc = __fadd_rn(acc, __fmul_rn(v1, v1));
    }
#pragma unroll
    for (int s = 16; s; s >>= 1)
        acc = __fadd_rn(acc, __shfl_xor_sync(0xffffffffu, acc, s));
    if (lane == 0) {
        if (which == 0) g_keynorm[warp] = acc;
        else            g_qnorm[warp]   = acc;
    }
}

// ---------------- K0b: fp32 -> bf16 conversion, 4 elems/thread --------------
__global__ void cvt_bf16(const float* __restrict__ src, __nv_bfloat16* __restrict__ dst,
                         int n_src, int n_dst) {
    int i4 = (blockIdx.x * blockDim.x + threadIdx.x) * 4;
    if (i4 >= n_dst) return;
    float4 v = make_float4(0.f, 0.f, 0.f, 0.f);
    if (i4 + 3 < n_src) v = *(const float4*)(src + i4);
    else {
        if (i4 + 0 < n_src) v.x = src[i4 + 0];
        if (i4 + 1 < n_src) v.y = src[i4 + 1];
        if (i4 + 2 < n_src) v.z = src[i4 + 2];
        if (i4 + 3 < n_src) v.w = src[i4 + 3];
    }
    __nv_bfloat162 p0 = __floats2bfloat162_rn(v.x, v.y);
    __nv_bfloat162 p1 = __floats2bfloat162_rn(v.z, v.w);
    *(uint2*)(dst + i4) = make_uint2(*(uint32_t*)&p0, *(uint32_t*)&p1);
}

// ---------------- K1: bf16 mma.sync screening GEMM, ldmatrix fragments ------
// CTA: 128 q x 128 k, 8 warps. Warp tile: 32m x 64n (warpM 0..3, warpN 0..1).
// s~ = qn - 2*dot_bf16 + kn (exact fp32 norms), fp16 store + 64-block mins.
// Epilogue stages the fp16 tile in smem, then writes coalesced streaming v4.
#define SAS 136   // smem row stride in halves (272B -> ldmatrix conflict-free)

static __device__ __forceinline__ void mma16816(float acc[4],
                                                uint32_t a0, uint32_t a1, uint32_t a2, uint32_t a3,
                                                uint32_t b0, uint32_t b1) {
    asm volatile(
        "mma.sync.aligned.m16n8k16.row.col.f32.bf16.bf16.f32 "
        "{%0,%1,%2,%3}, {%4,%5,%6,%7}, {%8,%9}, {%0,%1,%2,%3};\n"
        : "+f"(acc[0]), "+f"(acc[1]), "+f"(acc[2]), "+f"(acc[3])
        : "r"(a0), "r"(a1), "r"(a2), "r"(a3), "r"(b0), "r"(b1));
}
static __device__ __forceinline__ void ldsm_x4(uint32_t& r0, uint32_t& r1,
                                               uint32_t& r2, uint32_t& r3, uint32_t addr) {
    asm volatile("ldmatrix.sync.aligned.m8n8.x4.shared.b16 {%0,%1,%2,%3}, [%4];"
                 : "=r"(r0), "=r"(r1), "=r"(r2), "=r"(r3) : "r"(addr));
}

#define SMEM_TOT (2 * 128 * SAS * 2)   // A + B, 69632 B (staging reuses this)

__global__ __launch_bounds__(256) void screen_gemm() {
    extern __shared__ __align__(16) unsigned char smraw[];
    uint32_t smbA = smem_u32(smraw);
    uint32_t smbB = smbA + 128 * SAS * 2;

    int tid  = threadIdx.x;
    int wid  = tid >> 5;
    int lane = tid & 31;
    int warpM = wid & 3;   // 32 q rows each
    int warpN = wid >> 2;  // 64 k cols each
    int n0   = blockIdx.x * 128;
    int b0q  = blockIdx.y * 128;

    // stage A (128 q rows) and B (128 key rows), row-major, padded stride
    for (int i = tid; i < 128 * 16; i += 256) {
        int row = i >> 4, ch = i & 15;   // ch = 16B chunk (8 bf16)
        uint4 va = *(const uint4*)(g_Qb + (size_t)(b0q + row) * DIM + ch * 8);
        *(uint4*)(smraw + (row * SAS + ch * 8) * 2) = va;
        uint4 vb = *(const uint4*)(g_Kb + (size_t)(n0 + row) * DIM + ch * 8);
        *(uint4*)(smraw + 128 * SAS * 2 + (row * SAS + ch * 8) * 2) = vb;
    }
    __syncthreads();

    float acc[2][8][4];
#pragma unroll
    for (int mi = 0; mi < 2; mi++)
#pragma unroll
        for (int ni = 0; ni < 8; ni++)
#pragma unroll
            for (int j = 0; j < 4; j++) acc[mi][ni][j] = 0.f;

    int lj  = lane >> 3;
    int ljr = lane & 7;

#pragma unroll
    for (int ks = 0; ks < 8; ks++) {
        int k0 = ks * 16;
        uint32_t a[2][4];
#pragma unroll
        for (int mi = 0; mi < 2; mi++) {
            int arow = warpM * 32 + mi * 16 + (lj & 1) * 8 + ljr;
            uint32_t ad = smbA + (uint32_t)((arow * SAS + k0 + (lj >> 1) * 8) * 2);
            ldsm_x4(a[mi][0], a[mi][1], a[mi][2], a[mi][3], ad);
        }
        uint32_t bfr[4][4];
#pragma unroll
        for (int nj = 0; nj < 4; nj++) {
            int brow = warpN * 64 + nj * 16 + (lj >> 1) * 8 + ljr;
            uint32_t bd = smbB + (uint32_t)((brow * SAS + k0 + (lj & 1) * 8) * 2);
            ldsm_x4(bfr[nj][0], bfr[nj][1], bfr[nj][2], bfr[nj][3], bd);
        }
#pragma unroll
        for (int mi = 0; mi < 2; mi++)
#pragma unroll
            for (int nj = 0; nj < 4; nj++) {
                mma16816(acc[mi][2 * nj + 0], a[mi][0], a[mi][1], a[mi][2], a[mi][3],
                         bfr[nj][0], bfr[nj][1]);
                mma16816(acc[mi][2 * nj + 1], a[mi][0], a[mi][1], a[mi][2], a[mi][3],
                         bfr[nj][2], bfr[nj][3]);
            }
    }

    // ---- epilogue: compute s~, stage fp16 tile in smem, track block mins ----
    __syncthreads();   // done reading A/B tiles; reuse smraw as staging
    __half* stag = (__half*)smraw;   // [128][SAS] halves (conflict-free pad)

    int colbase = n0 + warpN * 64;
#pragma unroll
    for (int mi = 0; mi < 2; mi++) {
#pragma unroll
        for (int rr = 0; rr < 2; rr++) {
            int qloc = warpM * 32 + mi * 16 + rr * 8 + (lane >> 2);
            int q  = b0q + qloc;
            float qn = g_qnorm[q];
            float mn = finf();
#pragma unroll
            for (int ni = 0; ni < 8; ni++) {
                int gn = colbase + ni * 8 + 2 * (lane & 3);
                float d0 = acc[mi][ni][2 * rr + 0];
                float d1 = acc[mi][ni][2 * rr + 1];
                float s0 = (gn     < NK) ? (qn - 2.f * d0 + g_keynorm[gn])     : finf();
                float s1 = (gn + 1 < NK) ? (qn - 2.f * d1 + g_keynorm[gn + 1]) : finf();
                __half h0 = __float2half(s0), h1 = __float2half(s1);
                __half2 p; p.x = h0; p.y = h1;
                int cloc = warpN * 64 + ni * 8 + 2 * (lane & 3);
                *(__half2*)(stag + qloc * SAS + cloc) = p;
                mn = fminf(mn, fminf(__half2float(h0), __half2float(h1)));
            }
#pragma unroll
            for (int s = 1; s < 4; s <<= 1)
                mn = fminf(mn, __shfl_xor_sync(0xffffffffu, mn, s));
            if ((lane & 3) == 0)
                g_bmin[(size_t)q * NBLK + blockIdx.x * 2 + warpN] = mn;
        }
    }
    __syncthreads();

    // ---- coalesced streaming store of the 128x128 fp16 tile ----
    for (int i = tid; i < 128 * 16; i += 256) {
        int row = i >> 4, ch = i & 15;   // 16 x 16B chunks per 256B row
        uint4 v = *(const uint4*)(stag + row * SAS + ch * 8);
        stg_cs_v4(g_sh + (size_t)(b0q + row) * NKP + n0 + ch * 8, v);
    }
}

// ---------------- K2: select via screen + EXACT frozen-chain rescore --------
__global__ __launch_bounds__(256) void topk_sel(const float* __restrict__ Q,
                                                const float* __restrict__ Kd) {
    int b    = blockIdx.x;
    int tid  = threadIdx.x;
    int w    = tid >> 5;
    int lane = tid & 31;

    __shared__ float smin[256];
    __shared__ float sv[CAP];
    __shared__ int   si[CAP];
    __shared__ float qrow[DIM];
    __shared__ float kbuf[8][DIM];
    __shared__ int   s_cnt;

    const float* bm = g_bmin + (size_t)b * NBLK;

    // ---- pass 1: tau from block minima ----
    float m = finf();
    for (int p = tid; p < NBLK; p += 256) m = fminf(m, bm[p]);
    smin[tid] = m;
    if (tid == 0) s_cnt = 0;
    for (int k = tid; k < DIM; k += 256) qrow[k] = Q[(size_t)b * DIM + k];
    __syncthreads();

    for (int k = 2; k <= 256; k <<= 1) {
        for (int j = k >> 1; j; j >>= 1) {
            int ixj = tid ^ j;
            if (ixj > tid) {
                float v1 = smin[tid], v2 = smin[ixj];
                bool up = ((tid & k) == 0);
                if ((v1 < v2) != up) { smin[tid] = v2; smin[ixj] = v1; }
            }
            __syncthreads();
        }
    }
    float T2 = smin[TOPK - 1] + 2.f * MARG;   // superset threshold
    __syncthreads();

    // ---- pass 2: candidates from fp16 screen matrix (warp per block) ----
    const __half* srow = g_sh + (size_t)b * NKP;
    for (int p = w; p < NBLK; p += 8) {
        if (bm[p] <= T2) {
            int nb = p * 64 + lane * 2;
            __half2 h2 = *(const __half2*)(srow + nb);
            float f0 = __half2float(h2.x);
            float f1 = __half2float(h2.y);
            if (nb < NK && f0 <= T2) {
                int q = atomicAdd(&s_cnt, 1);
                if (q < CAP) si[q] = nb;
            }
            if (nb + 1 < NK && f1 <= T2) {
                int q = atomicAdd(&s_cnt, 1);
                if (q < CAP) si[q] = nb + 1;
            }
        }
    }
    __syncthreads();
    int cnt = s_cnt; if (cnt > CAP) cnt = CAP;

    // ---- exact rescore with the FROZEN chain (warp per candidate) ----
    float qn = g_qnorm[b];
    for (int c = w; c < cnt; c += 8) {
        int n = si[c];
        float4 kv = *(const float4*)(Kd + (size_t)n * DIM + lane * 4);
        *(float4*)&kbuf[w][lane * 4] = kv;
        __syncwarp();
        if (lane == 0) {
            float acc = 0.f;
#pragma unroll
            for (int k = 0; k < DIM; k++)
                acc = fmaf(qrow[k], kbuf[w][k], acc);   // ascending k, FMA — frozen
            sv[c] = __fadd_rn(__fsub_rn(qn, 2.f * acc), g_keynorm[n]);
        }
        __syncwarp();
    }
    __syncthreads();

    int P = 64; while (P < cnt) P <<= 1;
    for (int i = tid; i < P; i += 256)
        if (i >= cnt) { sv[i] = finf(); si[i] = 0x7fffffff; }
    __syncthreads();

    // bitonic sort by (value, index) ascending — canonical, deterministic
    for (int k = 2; k <= P; k <<= 1) {
        for (int j = k >> 1; j; j >>= 1) {
            for (int i = tid; i < P; i += 256) {
                int ixj = i ^ j;
                if (ixj > i) {
                    float v1 = sv[i], v2 = sv[ixj];
                    int  i1 = si[i],  i2 = si[ixj];
                    bool up   = ((i & k) == 0);
                    bool less = (v1 < v2) || (v1 == v2 && i1 < i2);
                    if (less != up) {
                        sv[i] = v2; sv[ixj] = v1;
                        si[i] = i2; si[ixj] = i1;
                    }
                }
            }
            __syncthreads();
        }
    }

    if (tid < TOPK) {
        int ki = si[tid];
        if (ki < 0) ki = 0;
        if (ki >= NK) ki = NK - 1;   // fail-soft: never emit OOB index
        g_topk[b * TOPK + tid] = ki;
    }
}

// ---------------- K3: fp32 recompute (as reference) + weighting (FROZEN) ----
__global__ __launch_bounds__(128) void out_kernel(const float* __restrict__ Q,
                                                  const float* __restrict__ Kd,
                                                  const float* __restrict__ V,
                                                  float* __restrict__ out) {
    int b    = blockIdx.x;
    int lane = threadIdx.x & 31;
    int warp = threadIdx.x >> 5;
    __shared__ float sqd[TOPK];

    const float* qr = Q + (size_t)b * DIM;
    for (int j = warp; j < TOPK; j += 4) {
        int ki = g_topk[b * TOPK + j];
        const float* kr = Kd + (size_t)ki * DIM;
        float acc = 0.f;
#pragma unroll
        for (int m = 0; m < 4; m++) {
            float d = qr[lane + 32 * m] - kr[lane + 32 * m];
            float p = __fmul_rn(d, d);
            acc = __fadd_rn(acc, p);
        }
#pragma unroll
        for (int s = 16; s; s >>= 1) acc += __shfl_xor_sync(0xffffffffu, acc, s);
        if (lane == 0) sqd[j] = acc;
    }
    __syncthreads();

    if (threadIdx.x == 0) {
        float s1 = 0.f, s2 = 0.f;
        for (int j = 0; j < TOPK; j++) {
            float w = 1.f / (sqd[j] + DELTA);
            s1 += w;
            s2 += w * V[g_topk[b * TOPK + j]];
        }
        out[b] = s2 / s1;
    }
}

// ---------------- launch ----------------------------------------------------
extern "C" void kernel_launch(void* const* d_in, const int* in_sizes, int n_in,
                              void* d_out, int out_size) {
    const float* Q  = nullptr;   // 262144 elems
    const float* Kd = nullptr;   // 12800000 elems
    const float* V  = nullptr;   // 100000 elems
    for (int i = 0; i < n_in; i++) {
        if      (in_sizes[i] == BQ * DIM) Q  = (const float*)d_in[i];
        else if (in_sizes[i] == NK * DIM) Kd = (const float*)d_in[i];
        else if (in_sizes[i] == NK)       V  = (const float*)d_in[i];
    }
    float* out = (float*)d_out;
    if (!Q || !Kd || !V) return;

    norms_kernel<<<(NK + 7) / 8, 256>>>(Kd, NK, 0);
    norms_kernel<<<(BQ + 7) / 8, 256>>>(Q,  BQ, 1);

    // bf16 copies (zero-padded keys)
    {
        __nv_bfloat16* qb = nullptr; cudaGetSymbolAddress((void**)&qb, g_Qb);
        __nv_bfloat16* kb = nullptr; cudaGetSymbolAddress((void**)&kb, g_Kb);
        int nq = BQ * DIM;
        int nk = NKP * DIM;
        cvt_bf16<<<(nq / 4 + 255) / 256, 256>>>(Q,  qb, nq,       nq);
        cvt_bf16<<<(nk / 4 + 255) / 256, 256>>>(Kd, kb, NK * DIM, nk);
    }

    static int smem_set = 0;
    if (!smem_set) {
        cudaFuncSetAttribute(screen_gemm, cudaFuncAttributeMaxDynamicSharedMemorySize,
                             SMEM_TOT);
        smem_set = 1;
    }
    dim3 sgrid(NKP / 128, BQ / 128);   // 782 x 16
    screen_gemm<<<sgrid, 256, SMEM_TOT>>>();

    topk_sel<<<BQ, 256>>>(Q, Kd);

    out_kernel<<<BQ, 128>>>(Q, Kd, V, out);
}